// round 4
// baseline (speedup 1.0000x reference)
#include <cuda_runtime.h>
#include <math.h>

#define Bsz 128
#define Tlen 48
#define Dm 512
#define NBLK 128
#define NTHR 1024

// ---------------- global scratch ---------------------------------------------
__device__ float g_w[Bsz*Tlen*64];
__device__ unsigned long long g_code[Bsz*Tlen*2];
__device__ int g_src[Bsz*Tlen];
__device__ float g_mem[Bsz*64*Dm];
__device__ float g_read[Bsz*Dm];
__device__ float g_f[Bsz*Dm];
__device__ float g_we[Bsz*Dm];
__device__ float g_ft[Tlen*Bsz*Dm];
__device__ float g_preF[Bsz*Tlen*Dm];     // k_emb @ WfR^T + bf   (rows b*T+t)
__device__ float g_preWE[Bsz*Tlen*Dm];    // y_emb @ WaR^T + ba   (rows b*T+t)
__device__ float g_pre[Tlen*Bsz*2048];    // ft @ Wih^T + bih + bhh (rows t*B+b)
__device__ float g_H[(Tlen+1)*Bsz*Dm];
__device__ float g_C[(Tlen+1)*Bsz*Dm];
__device__ unsigned g_count = 0;
__device__ volatile unsigned g_sense = 0;

__device__ __forceinline__ float sigm(float x) { return 1.0f / (1.0f + expf(-x)); }

// ---------------- smem layout (floats) ----------------------------------------
#define OFF_AS   0        // 512 x 20 (k-major A, 16 rows)  = 10240
#define OFF_WS   10240    // 18432: [512][36] fwe | [256][72] ea | [128][144] lstm | par/preG slices
#define OFF_PART 28672    // 32 x 16 x 36 = 18432
#define OFF_WT   47104    // 1024
#define OFF_WN   48128    // 1024
#define OFF_EA   49152    // 1024 (also softmax ivb bytes)
#define OFF_RP   50176    // 1024
#define OFF_I64  51200    // 64 ints
#define SMEM_FLOATS 51264
#define SMEM_BYTES (SMEM_FLOATS * 4)

// ---------------- grid-wide barrier -------------------------------------------
__device__ __forceinline__ void gsync(unsigned& ls) {
    __syncthreads();
    if (threadIdx.x == 0) {
        unsigned target = ls ^ 1u;
        __threadfence();
        if (atomicAdd(&g_count, 1u) == gridDim.x - 1) {
            atomicExch(&g_count, 0u);
            __threadfence();
            g_sense = target;
        } else {
            while (g_sense != target) { }
        }
        ls = target;
        __threadfence();
    }
    __syncthreads();
}

__device__ __forceinline__ void fma16(float (&acc)[4][4], float4 a, float4 w) {
    acc[0][0]=fmaf(a.x,w.x,acc[0][0]); acc[0][1]=fmaf(a.x,w.y,acc[0][1]);
    acc[0][2]=fmaf(a.x,w.z,acc[0][2]); acc[0][3]=fmaf(a.x,w.w,acc[0][3]);
    acc[1][0]=fmaf(a.y,w.x,acc[1][0]); acc[1][1]=fmaf(a.y,w.y,acc[1][1]);
    acc[1][2]=fmaf(a.y,w.z,acc[1][2]); acc[1][3]=fmaf(a.y,w.w,acc[1][3]);
    acc[2][0]=fmaf(a.z,w.x,acc[2][0]); acc[2][1]=fmaf(a.z,w.y,acc[2][1]);
    acc[2][2]=fmaf(a.z,w.z,acc[2][2]); acc[2][3]=fmaf(a.z,w.w,acc[2][3]);
    acc[3][0]=fmaf(a.w,w.x,acc[3][0]); acc[3][1]=fmaf(a.w,w.y,acc[3][1]);
    acc[3][2]=fmaf(a.w,w.z,acc[3][2]); acc[3][3]=fmaf(a.w,w.w,acc[3][3]);
}

// ---------------- upfront parallel GEMMs: preF, preWE, addr -------------------
// tiles 64x64 (addr: 64x64 with N=64): A = gathered table rows, C = A @ W^T
__device__ void stage_par(float* sm,
                          const float* __restrict__ ktab, const float* __restrict__ xtab,
                          const int* __restrict__ q, const int* __restrict__ r,
                          const float* __restrict__ Wf, const float* __restrict__ bf,
                          const float* __restrict__ Wa, const float* __restrict__ ba,
                          const float* __restrict__ Mk)
{
    float* As = sm + OFF_AS;   // [64][36] row-major (k-local in row)
    float* Ws = sm + OFF_WS;   // [32][68]
    int* sIdx = (int*)(sm + OFF_I64);
    const int tid = threadIdx.x;
    const int ty = tid >> 4, tx = tid & 15;
    for (int tile = blockIdx.x; tile < 1632; tile += NBLK) {
        int seg, row0, cc0;
        if (tile < 768)       { seg = 0; row0 = (tile >> 3) * 64; cc0 = (tile & 7) * 64; }
        else if (tile < 1536) { int tl = tile - 768;  seg = 1; row0 = (tl >> 3) * 64; cc0 = (tl & 7) * 64; }
        else                  { int tl = tile - 1536; seg = 2; row0 = tl * 64; cc0 = 0; }
        if (tid < 64) {
            int rid = row0 + tid;
            int qi = q[rid];
            sIdx[tid] = (seg == 1) ? (qi + 2000 * r[rid]) : qi;
        }
        __syncthreads();
        float a0 = 0.f, a1 = 0.f, a2 = 0.f, a3 = 0.f;
        for (int ch = 0; ch < 16; ch++) {
            const int kb = ch * 32;
            if (tid < 512) {
                int rr = tid >> 3, kq = tid & 7;
                const float* tab = (seg == 1) ? xtab : ktab;
                float4 v = *(const float4*)(tab + (size_t)sIdx[rr] * Dm + kb + kq * 4);
                *(float4*)(As + rr * 36 + kq * 4) = v;
            } else {
                int i = tid - 512;
                int n = i & 63, kq = i >> 6;
                float4 v;
                if (seg == 0)      v = *(const float4*)(Wf + (size_t)(cc0 + n) * 1024 + 512 + kb + kq * 4);
                else if (seg == 1) v = *(const float4*)(Wa + (size_t)(cc0 + n) * 1024 + 512 + kb + kq * 4);
                else               v = *(const float4*)(Mk + (size_t)(cc0 + n) * 512 + kb + kq * 4);
                float* w = Ws + (kq * 4) * 68 + n;
                w[0] = v.x; w[68] = v.y; w[136] = v.z; w[204] = v.w;
            }
            __syncthreads();
#pragma unroll
            for (int c = 0; c < 32; c++) {
                float a = As[ty * 36 + c];
                float4 w4 = *(const float4*)(Ws + c * 68 + tx * 4);
                a0 = fmaf(a, w4.x, a0); a1 = fmaf(a, w4.y, a1);
                a2 = fmaf(a, w4.z, a2); a3 = fmaf(a, w4.w, a3);
            }
            __syncthreads();
        }
        const int row = row0 + ty, col = cc0 + tx * 4;
        if (seg == 0) {
            *(float4*)(g_preF + (size_t)row * Dm + col) =
                make_float4(a0 + bf[col], a1 + bf[col+1], a2 + bf[col+2], a3 + bf[col+3]);
        } else if (seg == 1) {
            *(float4*)(g_preWE + (size_t)row * Dm + col) =
                make_float4(a0 + ba[col], a1 + ba[col+1], a2 + ba[col+2], a3 + ba[col+3]);
        } else {
            *(float4*)(g_w + (size_t)row * 64 + col) = make_float4(a0, a1, a2, a3);
        }
    }
}

// ---------------- softmax + membership codes ----------------------------------
__device__ void stage_softmax(float* sm)
{
    unsigned char* ivb = (unsigned char*)(sm + OFF_EA);   // [32][64]
    const int wp = threadIdx.x >> 5, lane = threadIdx.x & 31;
    for (int rr = wp; rr < 48; rr += 32) {
        const int row = blockIdx.x * 48 + rr;
        float v0 = g_w[row * 64 + lane];
        float v1 = g_w[row * 64 + 32 + lane];
        float mx = fmaxf(v0, v1);
        for (int o = 16; o; o >>= 1) mx = fmaxf(mx, __shfl_xor_sync(0xffffffffu, mx, o));
        float e0 = expf(v0 - mx), e1 = expf(v1 - mx);
        float ss = e0 + e1;
        for (int o = 16; o; o >>= 1) ss += __shfl_xor_sync(0xffffffffu, ss, o);
        float inv = 1.0f / ss;
        float w0 = e0 * inv, w1 = e1 * inv;
        g_w[row * 64 + lane] = w0;
        g_w[row * 64 + 32 + lane] = w1;
        auto ivf = [](float w) -> int {
            float m = fmaxf(fminf((w - 0.075f) / (0.088f - 0.075f),
                                  (1.0f - w) / (1.0f - 0.088f)), 0.0f);
            return (m >= 0.6f) ? 2 : ((m >= 0.1f) ? 1 : 0);
        };
        ivb[wp * 64 + lane] = (unsigned char)ivf(w0);
        ivb[wp * 64 + 32 + lane] = (unsigned char)ivf(w1);
        __syncwarp();
        if (lane == 0) {
            unsigned long long c0 = 0ull, c1 = 0ull;
            for (int i = 0; i < 32; i++) {
                c0 |= (unsigned long long)ivb[wp * 64 + i] << (2 * i);
                c1 |= (unsigned long long)ivb[wp * 64 + 32 + i] << (2 * i);
            }
            g_code[row * 2] = c0;
            g_code[row * 2 + 1] = c1;
        }
        __syncwarp();
    }
}

// ---------------- src scan + g_mem / H0 / C0 / read0 init --------------------
__device__ void stage_init(float* sm, const float* __restrict__ Mv0,
                           const float* __restrict__ hx0, const float* __restrict__ cx0,
                           int r0, int c0)
{
    float* wT = sm + OFF_WT;
    const int tid = threadIdx.x;
    if (tid < Tlen) {
        const int b = blockIdx.x, i = tid;
        unsigned long long cc0v = g_code[(b * Tlen + i) * 2];
        unsigned long long cc1v = g_code[(b * Tlen + i) * 2 + 1];
        int sv = i - 1;
        for (int j = i - 1; j >= 0; j--)
            if (g_code[(b * Tlen + j) * 2] == cc0v && g_code[(b * Tlen + j) * 2 + 1] == cc1v) { sv = j; break; }
        g_src[b * Tlen + i] = sv;
    }
    {
        int bl = tid >> 6, m = tid & 63;
        wT[tid] = g_w[((r0 + bl) * Tlen) * 64 + m];
    }
    // mem slice init: 16 rows x 64 m x 32 cc = 32768 elements
#pragma unroll
    for (int it = 0; it < 32; it++) {
        int i2 = tid + it * NTHR;
        int rr = i2 >> 11, rem = i2 & 2047;
        int m = rem >> 5, cc = rem & 31;
        g_mem[(((size_t)(r0 + rr)) * 64 + m) * Dm + c0 + cc] = Mv0[m * Dm + c0 + cc];
    }
    __syncthreads();
    if (tid < 512) {
        int rr = tid >> 5, cc = tid & 31;
        int b = r0 + rr, col = c0 + cc;
        g_H[(size_t)b * Dm + col] = hx0[col];
        g_C[(size_t)b * Dm + col] = cx0[col];
        float racc = 0.f;
#pragma unroll 4
        for (int m = 0; m < 64; m++)
            racc = fmaf(wT[rr * 64 + m], Mv0[m * Dm + col], racc);
        g_read[(size_t)b * Dm + col] = racc;
    }
}

// ---------------- f / we stage: C[16,32] = A[16,512] @ W[:, :512]^T + pre ----
template<int MODE>  // 0: A=g_read, W=Wf, out tanh -> g_f,g_ft ; 1: A=g_f, W=Wa -> g_we
__device__ void stage_fwe(float* sm, const float* __restrict__ W, int t, int r0, int c0)
{
    float* As = sm + OFF_AS;
    float* Ws = sm + OFF_WS;
    float* part = sm + OFF_PART;
    const int tid = threadIdx.x;
    const float* A = (MODE == 0) ? g_read : g_f;
#pragma unroll
    for (int h = 0; h < 2; h++) {
        int i = tid + h * NTHR;
        int rr = i & 15, kq = i >> 4;
        float4 v = *(const float4*)(A + (size_t)(r0 + rr) * Dm + kq * 4);
        float* a = As + (kq * 4) * 20 + rr;
        a[0] = v.x; a[20] = v.y; a[40] = v.z; a[60] = v.w;
    }
#pragma unroll
    for (int h = 0; h < 4; h++) {
        int i = tid + h * NTHR;
        int n = i & 31, kq = i >> 5;
        float4 v = *(const float4*)(W + (size_t)(c0 + n) * 1024 + kq * 4);
        float* w = Ws + (kq * 4) * 36 + n;
        w[0] = v.x; w[36] = v.y; w[72] = v.z; w[108] = v.w;
    }
    __syncthreads();
    const int s = tid >> 5, pos = tid & 31, rg = pos >> 3, cg = pos & 7;
    float acc[4][4] = {};
#pragma unroll
    for (int kk = 0; kk < 16; kk++) {
        int k = s * 16 + kk;
        float4 a4 = *(const float4*)(As + k * 20 + rg * 4);
        float4 w4 = *(const float4*)(Ws + k * 36 + cg * 4);
        fma16(acc, a4, w4);
    }
#pragma unroll
    for (int j = 0; j < 4; j++)
        *(float4*)(part + s * 576 + (rg * 4 + j) * 36 + cg * 4) =
            make_float4(acc[j][0], acc[j][1], acc[j][2], acc[j][3]);
    __syncthreads();
    if (tid < 512) {
        int rr = tid >> 5, cc = tid & 31;
        float v = 0.f;
#pragma unroll
        for (int p = 0; p < 32; p++) v += part[p * 576 + rr * 36 + cc];
        int b = r0 + rr, col = c0 + cc;
        if (MODE == 0) {
            v += g_preF[((size_t)b * Tlen + t) * Dm + col];
            v = tanhf(v);
            g_f[(size_t)b * Dm + col] = v;
            g_ft[((size_t)t * Bsz + b) * Dm + col] = v;
        } else {
            v += g_preWE[((size_t)b * Tlen + t) * Dm + col];
            g_we[(size_t)b * Dm + col] = v;
        }
    }
}

// ---------------- e/a GEMMs + memory update + fused read_{t+1} ----------------
__device__ void stage_ea(float* sm, const float* __restrict__ We, const float* __restrict__ be,
                         const float* __restrict__ Wadd, const float* __restrict__ badd,
                         int t, int r0, int c0)
{
    float* As = sm + OFF_AS;
    float* Ws = sm + OFF_WS;     // [256][72] per chunk: e cols [0,36), a cols [36,72)
    float* part = sm + OFF_PART;
    float* wT = sm + OFF_WT;
    float* wN = sm + OFF_WN;
    float* EA = sm + OFF_EA;
    float* RP = sm + OFF_RP;
    const int tid = threadIdx.x;
    {
        int bl = tid >> 6, m = tid & 63;
        wT[tid] = g_w[((r0 + bl) * Tlen + t) * 64 + m];
        wN[tid] = (t + 1 < Tlen) ? g_w[((r0 + bl) * Tlen + t + 1) * 64 + m] : 0.0f;
    }
#pragma unroll
    for (int h = 0; h < 2; h++) {
        int i = tid + h * NTHR;
        int rr = i & 15, kq = i >> 4;
        float4 v = *(const float4*)(g_we + (size_t)(r0 + rr) * Dm + kq * 4);
        float* a = As + (kq * 4) * 20 + rr;
        a[0] = v.x; a[20] = v.y; a[40] = v.z; a[60] = v.w;
    }
    const int hh = tid >> 9, sub = (tid >> 5) & 15, pos = tid & 31, rg = pos >> 3, cg = pos & 7;
    float acc[4][4] = {};
    for (int c2 = 0; c2 < 2; c2++) {
        const int kb = c2 * 256;
#pragma unroll
        for (int h = 0; h < 4; h++) {
            int i = tid + h * NTHR;
            int n2 = i & 63, kq = i >> 6;
            const float* Wp2 = (n2 < 32) ? We : Wadd;
            int n = (n2 < 32) ? n2 : n2 - 32;
            int wc = (n2 < 32) ? n2 : 36 + n2 - 32;
            float4 v = *(const float4*)(Wp2 + (size_t)(c0 + n) * Dm + kb + kq * 4);
            float* w = Ws + (kq * 4) * 72 + wc;
            w[0] = v.x; w[72] = v.y; w[144] = v.z; w[216] = v.w;
        }
        __syncthreads();
#pragma unroll
        for (int kk = 0; kk < 16; kk++) {
            int kl = sub * 16 + kk;
            float4 a4 = *(const float4*)(As + (kb + kl) * 20 + rg * 4);
            float4 w4 = *(const float4*)(Ws + kl * 72 + hh * 36 + cg * 4);
            fma16(acc, a4, w4);
        }
        __syncthreads();
    }
    const int slot = hh * 16 + sub;
#pragma unroll
    for (int j = 0; j < 4; j++)
        *(float4*)(part + slot * 576 + (rg * 4 + j) * 36 + cg * 4) =
            make_float4(acc[j][0], acc[j][1], acc[j][2], acc[j][3]);
    __syncthreads();
    if (tid < 512) {
        int rr = tid >> 5, cc = tid & 31;
        float ve = 0.f, va = 0.f;
#pragma unroll
        for (int p = 0; p < 16; p++)  ve += part[p * 576 + rr * 36 + cc];
#pragma unroll
        for (int p = 16; p < 32; p++) va += part[p * 576 + rr * 36 + cc];
        EA[tid] = sigm(ve + be[c0 + cc]);
        EA[512 + tid] = tanhf(va + badd[c0 + cc]);
    }
    __syncthreads();
    {
        int oid = tid & 511, mh = tid >> 9;
        int rr = oid >> 5, cc = oid & 31;
        float e = EA[oid], a = EA[512 + oid];
        float racc = 0.f;
        size_t base = ((size_t)(r0 + rr) * 64) * Dm + c0 + cc;
#pragma unroll 4
        for (int mi = 0; mi < 32; mi++) {
            int m = mh * 32 + mi;
            float wt = wT[rr * 64 + m], wn = wN[rr * 64 + m];
            float* p = g_mem + base + (size_t)m * Dm;
            float v = *p;
            v = v * (1.0f - wt * e) + wt * a;
            *p = v;
            racc = fmaf(wn, v, racc);
        }
        RP[tid] = racc;
    }
    __syncthreads();
    if (tid < 512) {
        int rr = tid >> 5, cc = tid & 31;
        g_read[(size_t)(r0 + rr) * Dm + c0 + cc] = RP[tid] + RP[512 + tid];
    }
}

// ---------------- parallel GEMM between loops: g_pre = ft @ Wih^T + biases ----
__device__ void stage_preG(float* sm, const float* __restrict__ Wih,
                           const float* __restrict__ bih, const float* __restrict__ bhh)
{
    float* As = sm + OFF_AS;   // [64][36]
    float* Ws = sm + OFF_WS;   // [32][68]
    const int tid = threadIdx.x;
    const int ty = tid >> 4, tx = tid & 15;
    for (int tile = blockIdx.x; tile < 3072; tile += NBLK) {
        const int row0 = (tile >> 5) * 64, cc0 = (tile & 31) * 64;
        float a0 = 0.f, a1 = 0.f, a2 = 0.f, a3 = 0.f;
        for (int ch = 0; ch < 16; ch++) {
            const int kb = ch * 32;
            if (tid < 512) {
                int rr = tid >> 3, kq = tid & 7;
                float4 v = *(const float4*)(g_ft + (size_t)(row0 + rr) * Dm + kb + kq * 4);
                *(float4*)(As + rr * 36 + kq * 4) = v;
            } else {
                int i = tid - 512;
                int n = i & 63, kq = i >> 6;
                float4 v = *(const float4*)(Wih + (size_t)(cc0 + n) * Dm + kb + kq * 4);
                float* w = Ws + (kq * 4) * 68 + n;
                w[0] = v.x; w[68] = v.y; w[136] = v.z; w[204] = v.w;
            }
            __syncthreads();
#pragma unroll
            for (int c = 0; c < 32; c++) {
                float a = As[ty * 36 + c];
                float4 w4 = *(const float4*)(Ws + c * 68 + tx * 4);
                a0 = fmaf(a, w4.x, a0); a1 = fmaf(a, w4.y, a1);
                a2 = fmaf(a, w4.z, a2); a3 = fmaf(a, w4.w, a3);
            }
            __syncthreads();
        }
        const int row = row0 + ty, col = cc0 + tx * 4;
        *(float4*)(g_pre + (size_t)row * 2048 + col) =
            make_float4(a0 + bih[col] + bhh[col],     a1 + bih[col+1] + bhh[col+1],
                        a2 + bih[col+2] + bhh[col+2], a3 + bih[col+3] + bhh[col+3]);
    }
}

// ---------------- hop-LSTM step: gates = h_src @ Whh^T + g_pre ----------------
__device__ void stage_lstm(float* sm, const float* __restrict__ Whh, int t, int r0, int c0)
{
    float* As = sm + OFF_AS;
    float* Ws = sm + OFF_WS;   // [128][144] per chunk: gate g cols at [k][g*36 + n]
    float* part = sm + OFF_PART;
    int* s16 = (int*)(sm + OFF_I64);
    const int tid = threadIdx.x;
    if (tid < 16) s16[tid] = g_src[(r0 + tid) * Tlen + t] + 1;
    __syncthreads();
#pragma unroll
    for (int h = 0; h < 2; h++) {
        int i = tid + h * NTHR;
        int rr = i & 15, kq = i >> 4;
        float4 v = *(const float4*)(g_H + ((size_t)s16[rr] * Bsz + r0 + rr) * Dm + kq * 4);
        float* a = As + (kq * 4) * 20 + rr;
        a[0] = v.x; a[20] = v.y; a[40] = v.z; a[60] = v.w;
    }
    const int gate = tid >> 8, sub = (tid >> 5) & 7, pos = tid & 31, rg = pos >> 3, cg = pos & 7;
    float acc[4][4] = {};
    for (int c4 = 0; c4 < 4; c4++) {
        const int kb = c4 * 128;
#pragma unroll
        for (int h = 0; h < 4; h++) {
            int i = tid + h * NTHR;
            int col = i & 127, kq = i >> 7;
            int g2 = col >> 5, n = col & 31;
            float4 v = *(const float4*)(Whh + (size_t)(g2 * Dm + c0 + n) * Dm + kb + kq * 4);
            float* w = Ws + (kq * 4) * 144 + g2 * 36 + n;
            w[0] = v.x; w[144] = v.y; w[288] = v.z; w[432] = v.w;
        }
        __syncthreads();
#pragma unroll
        for (int kk = 0; kk < 16; kk++) {
            int kl = sub * 16 + kk;
            float4 a4 = *(const float4*)(As + (kb + kl) * 20 + rg * 4);
            float4 w4 = *(const float4*)(Ws + kl * 144 + gate * 36 + cg * 4);
            fma16(acc, a4, w4);
        }
        __syncthreads();
    }
    const int slot = gate * 8 + sub;
#pragma unroll
    for (int j = 0; j < 4; j++)
        *(float4*)(part + slot * 576 + (rg * 4 + j) * 36 + cg * 4) =
            make_float4(acc[j][0], acc[j][1], acc[j][2], acc[j][3]);
    __syncthreads();
    if (tid < 512) {
        int rr = tid >> 5, cc = tid & 31;
        float gs[4];
#pragma unroll
        for (int g2 = 0; g2 < 4; g2++) {
            float v = 0.f;
#pragma unroll
            for (int p = g2 * 8; p < g2 * 8 + 8; p++) v += part[p * 576 + rr * 36 + cc];
            gs[g2] = v;
        }
        const int b = r0 + rr, col = c0 + cc;
        const float* pre = g_pre + ((size_t)t * Bsz + b) * 2048;
        float gi = gs[0] + pre[col];
        float gf = gs[1] + pre[512 + col];
        float gg = gs[2] + pre[1024 + col];
        float go = gs[3] + pre[1536 + col];
        float cin = g_C[((size_t)s16[rr] * Bsz + b) * Dm + col];
        float cn = sigm(gf) * cin + sigm(gi) * tanhf(gg);
        float hn = sigm(go) * tanhf(cn);
        g_C[((size_t)(t + 1) * Bsz + b) * Dm + col] = cn;
        g_H[((size_t)(t + 1) * Bsz + b) * Dm + col] = hn;
    }
}

// ---------------- prediction head ---------------------------------------------
__device__ void stage_head(const float* __restrict__ Wp, const float* __restrict__ bp,
                           float* __restrict__ out)
{
    const int wp = threadIdx.x >> 5, lane = threadIdx.x & 31;
    for (int bt = blockIdx.x * 32 + wp; bt < Bsz * Tlen; bt += NBLK * 32) {
        const int b = bt / Tlen, t = bt % Tlen;
        const float* h = &g_H[((size_t)(t + 1) * Bsz + b) * Dm];
        float s = 0.f;
        for (int i = lane; i < Dm; i += 32) s = fmaf(h[i], Wp[i], s);
        for (int o = 16; o; o >>= 1) s += __shfl_xor_sync(0xffffffffu, s, o);
        if (lane == 0) out[bt] = sigm(s + bp[0]);
    }
}

// ---------------- the single persistent kernel --------------------------------
__global__ void __launch_bounds__(NTHR, 1) k_persist(
    const int* __restrict__ q, const int* __restrict__ r,
    const float* __restrict__ Mk, const float* __restrict__ Mv0,
    const float* __restrict__ ktab, const float* __restrict__ xtab,
    const float* __restrict__ We, const float* __restrict__ be,
    const float* __restrict__ Wadd, const float* __restrict__ badd,
    const float* __restrict__ Wa, const float* __restrict__ ba,
    const float* __restrict__ Wf, const float* __restrict__ bf,
    const float* __restrict__ Wih, const float* __restrict__ Whh,
    const float* __restrict__ bih, const float* __restrict__ bhh,
    const float* __restrict__ hx0, const float* __restrict__ cx0,
    const float* __restrict__ Wp, const float* __restrict__ bp,
    float* __restrict__ out)
{
    extern __shared__ float sm[];
    unsigned ls = 0;
    if (threadIdx.x == 0) ls = g_sense;
    const int r0 = (blockIdx.x & 7) * 16;
    const int c0 = (blockIdx.x >> 3) * 32;

    stage_par(sm, ktab, xtab, q, r, Wf, bf, Wa, ba, Mk);   gsync(ls);
    stage_softmax(sm);                                     gsync(ls);
    stage_init(sm, Mv0, hx0, cx0, r0, c0);                 gsync(ls);

    for (int t = 0; t < Tlen; t++) {
        stage_fwe<0>(sm, Wf, t, r0, c0);                   gsync(ls);
        stage_fwe<1>(sm, Wa, t, r0, c0);                   gsync(ls);
        stage_ea(sm, We, be, Wadd, badd, t, r0, c0);       gsync(ls);
    }
    stage_preG(sm, Wih, bih, bhh);                         gsync(ls);
    for (int t = 0; t < Tlen; t++) {
        stage_lstm(sm, Whh, t, r0, c0);                    gsync(ls);
    }
    stage_head(Wp, bp, out);
}

// ----------------------------------------------------------------------------
extern "C" void kernel_launch(void* const* d_in, const int* in_sizes, int n_in,
                              void* d_out, int out_size)
{
    const int*   q    = (const int*)d_in[0];
    const int*   r    = (const int*)d_in[1];
    const float* Mk   = (const float*)d_in[2];
    const float* Mv0  = (const float*)d_in[3];
    const float* ktab = (const float*)d_in[4];
    const float* xtab = (const float*)d_in[5];
    const float* We   = (const float*)d_in[6];
    const float* be   = (const float*)d_in[7];
    const float* Wadd = (const float*)d_in[8];
    const float* badd = (const float*)d_in[9];
    const float* Wa   = (const float*)d_in[10];
    const float* ba   = (const float*)d_in[11];
    const float* Wf   = (const float*)d_in[12];
    const float* bf   = (const float*)d_in[13];
    const float* Wih  = (const float*)d_in[14];
    const float* Whh  = (const float*)d_in[15];
    const float* bih  = (const float*)d_in[16];
    const float* bhh  = (const float*)d_in[17];
    const float* hx0  = (const float*)d_in[18];
    const float* cx0  = (const float*)d_in[19];
    const float* Wp   = (const float*)d_in[20];
    const float* bp   = (const float*)d_in[21];
    float* out = (float*)d_out;

    static bool attr_set = false;
    if (!attr_set) {
        cudaFuncSetAttribute(k_persist, cudaFuncAttributeMaxDynamicSharedMemorySize, SMEM_BYTES);
        attr_set = true;
    }
    k_persist<<<NBLK, NTHR, SMEM_BYTES>>>(q, r, Mk, Mv0, ktab, xtab, We, be, Wadd, badd,
                                          Wa, ba, Wf, bf, Wih, Whh, bih, bhh,
                                          hx0, cx0, Wp, bp, out);
}

// round 5
// speedup vs baseline: 1.0003x; 1.0003x over previous
#include <cuda_runtime.h>
#include <math.h>

#define Bsz 128
#define Tlen 48
#define Dm 512
#define NBLK 128
#define NTHR 1024

// ---------------- global scratch ---------------------------------------------
__device__ float g_w[Bsz*Tlen*64];
__device__ unsigned long long g_code[Bsz*Tlen*2];
__device__ int g_src[Bsz*Tlen];
__device__ float g_mem[Bsz*64*Dm];
__device__ float g_read[Bsz*Dm];
__device__ float g_f[Bsz*Dm];
__device__ float g_we[Bsz*Dm];
__device__ float g_ft[Tlen*Bsz*Dm];
__device__ float g_preF[Bsz*Tlen*Dm];     // k_emb @ WfR^T + bf   (rows b*T+t)
__device__ float g_preWE[Bsz*Tlen*Dm];    // y_emb @ WaR^T + ba   (rows b*T+t)
__device__ float g_pre[Tlen*Bsz*2048];    // ft @ Wih^T + bih + bhh (rows t*B+b)
__device__ float g_H[(Tlen+1)*Bsz*Dm];
__device__ float g_C[(Tlen+1)*Bsz*Dm];
__device__ unsigned g_count = 0;
__device__ volatile unsigned g_sense = 0;

__device__ __forceinline__ float sigm(float x) { return 1.0f / (1.0f + expf(-x)); }

// ---------------- smem layout (floats) ----------------------------------------
#define OFF_AS   0        // 512 x 20 (k-major A, 16 rows)  = 10240
#define OFF_WS   10240    // 18432: [512][36] fwe | [256][72] ea | [128][144] lstm | par/preG slices
#define OFF_PART 28672    // 32 x 16 x 36 = 18432
#define OFF_WT   47104    // 1024
#define OFF_WN   48128    // 1024
#define OFF_EA   49152    // 1024 (also softmax ivb bytes)
#define OFF_RP   50176    // 1024
#define OFF_I64  51200    // 64 ints
#define SMEM_FLOATS 51264
#define SMEM_BYTES (SMEM_FLOATS * 4)

// ---------------- grid-wide barrier -------------------------------------------
__device__ __forceinline__ void gsync(unsigned& ls) {
    __syncthreads();
    if (threadIdx.x == 0) {
        unsigned target = ls ^ 1u;
        __threadfence();
        if (atomicAdd(&g_count, 1u) == gridDim.x - 1) {
            atomicExch(&g_count, 0u);
            __threadfence();
            g_sense = target;
        } else {
            while (g_sense != target) { }
        }
        ls = target;
        __threadfence();
    }
    __syncthreads();
}

__device__ __forceinline__ void fma16(float (&acc)[4][4], float4 a, float4 w) {
    acc[0][0]=fmaf(a.x,w.x,acc[0][0]); acc[0][1]=fmaf(a.x,w.y,acc[0][1]);
    acc[0][2]=fmaf(a.x,w.z,acc[0][2]); acc[0][3]=fmaf(a.x,w.w,acc[0][3]);
    acc[1][0]=fmaf(a.y,w.x,acc[1][0]); acc[1][1]=fmaf(a.y,w.y,acc[1][1]);
    acc[1][2]=fmaf(a.y,w.z,acc[1][2]); acc[1][3]=fmaf(a.y,w.w,acc[1][3]);
    acc[2][0]=fmaf(a.z,w.x,acc[2][0]); acc[2][1]=fmaf(a.z,w.y,acc[2][1]);
    acc[2][2]=fmaf(a.z,w.z,acc[2][2]); acc[2][3]=fmaf(a.z,w.w,acc[2][3]);
    acc[3][0]=fmaf(a.w,w.x,acc[3][0]); acc[3][1]=fmaf(a.w,w.y,acc[3][1]);
    acc[3][2]=fmaf(a.w,w.z,acc[3][2]); acc[3][3]=fmaf(a.w,w.w,acc[3][3]);
}

// ---------------- upfront parallel GEMMs: preF, preWE, addr -------------------
// tiles 64x64 (addr: 64x64 with N=64): A = gathered table rows, C = A @ W^T
__device__ void stage_par(float* sm,
                          const float* __restrict__ ktab, const float* __restrict__ xtab,
                          const int* __restrict__ q, const int* __restrict__ r,
                          const float* __restrict__ Wf, const float* __restrict__ bf,
                          const float* __restrict__ Wa, const float* __restrict__ ba,
                          const float* __restrict__ Mk)
{
    float* As = sm + OFF_AS;   // [64][36] row-major (k-local in row)
    float* Ws = sm + OFF_WS;   // [32][68]
    int* sIdx = (int*)(sm + OFF_I64);
    const int tid = threadIdx.x;
    const int ty = tid >> 4, tx = tid & 15;
    for (int tile = blockIdx.x; tile < 1632; tile += NBLK) {
        int seg, row0, cc0;
        if (tile < 768)       { seg = 0; row0 = (tile >> 3) * 64; cc0 = (tile & 7) * 64; }
        else if (tile < 1536) { int tl = tile - 768;  seg = 1; row0 = (tl >> 3) * 64; cc0 = (tl & 7) * 64; }
        else                  { int tl = tile - 1536; seg = 2; row0 = tl * 64; cc0 = 0; }
        if (tid < 64) {
            int rid = row0 + tid;
            int qi = q[rid];
            sIdx[tid] = (seg == 1) ? (qi + 2000 * r[rid]) : qi;
        }
        __syncthreads();
        float a0 = 0.f, a1 = 0.f, a2 = 0.f, a3 = 0.f;
        for (int ch = 0; ch < 16; ch++) {
            const int kb = ch * 32;
            if (tid < 512) {
                int rr = tid >> 3, kq = tid & 7;
                const float* tab = (seg == 1) ? xtab : ktab;
                float4 v = *(const float4*)(tab + (size_t)sIdx[rr] * Dm + kb + kq * 4);
                *(float4*)(As + rr * 36 + kq * 4) = v;
            } else {
                int i = tid - 512;
                int n = i & 63, kq = i >> 6;
                float4 v;
                if (seg == 0)      v = *(const float4*)(Wf + (size_t)(cc0 + n) * 1024 + 512 + kb + kq * 4);
                else if (seg == 1) v = *(const float4*)(Wa + (size_t)(cc0 + n) * 1024 + 512 + kb + kq * 4);
                else               v = *(const float4*)(Mk + (size_t)(cc0 + n) * 512 + kb + kq * 4);
                float* w = Ws + (kq * 4) * 68 + n;
                w[0] = v.x; w[68] = v.y; w[136] = v.z; w[204] = v.w;
            }
            __syncthreads();
#pragma unroll
            for (int c = 0; c < 32; c++) {
                float a = As[ty * 36 + c];
                float4 w4 = *(const float4*)(Ws + c * 68 + tx * 4);
                a0 = fmaf(a, w4.x, a0); a1 = fmaf(a, w4.y, a1);
                a2 = fmaf(a, w4.z, a2); a3 = fmaf(a, w4.w, a3);
            }
            __syncthreads();
        }
        const int row = row0 + ty, col = cc0 + tx * 4;
        if (seg == 0) {
            *(float4*)(g_preF + (size_t)row * Dm + col) =
                make_float4(a0 + bf[col], a1 + bf[col+1], a2 + bf[col+2], a3 + bf[col+3]);
        } else if (seg == 1) {
            *(float4*)(g_preWE + (size_t)row * Dm + col) =
                make_float4(a0 + ba[col], a1 + ba[col+1], a2 + ba[col+2], a3 + ba[col+3]);
        } else {
            *(float4*)(g_w + (size_t)row * 64 + col) = make_float4(a0, a1, a2, a3);
        }
    }
}

// ---------------- softmax + membership codes ----------------------------------
__device__ void stage_softmax(float* sm)
{
    unsigned char* ivb = (unsigned char*)(sm + OFF_EA);   // [32][64]
    const int wp = threadIdx.x >> 5, lane = threadIdx.x & 31;
    for (int rr = wp; rr < 48; rr += 32) {
        const int row = blockIdx.x * 48 + rr;
        float v0 = g_w[row * 64 + lane];
        float v1 = g_w[row * 64 + 32 + lane];
        float mx = fmaxf(v0, v1);
        for (int o = 16; o; o >>= 1) mx = fmaxf(mx, __shfl_xor_sync(0xffffffffu, mx, o));
        float e0 = expf(v0 - mx), e1 = expf(v1 - mx);
        float ss = e0 + e1;
        for (int o = 16; o; o >>= 1) ss += __shfl_xor_sync(0xffffffffu, ss, o);
        float inv = 1.0f / ss;
        float w0 = e0 * inv, w1 = e1 * inv;
        g_w[row * 64 + lane] = w0;
        g_w[row * 64 + 32 + lane] = w1;
        auto ivf = [](float w) -> int {
            float m = fmaxf(fminf((w - 0.075f) / (0.088f - 0.075f),
                                  (1.0f - w) / (1.0f - 0.088f)), 0.0f);
            return (m >= 0.6f) ? 2 : ((m >= 0.1f) ? 1 : 0);
        };
        ivb[wp * 64 + lane] = (unsigned char)ivf(w0);
        ivb[wp * 64 + 32 + lane] = (unsigned char)ivf(w1);
        __syncwarp();
        if (lane == 0) {
            unsigned long long c0 = 0ull, c1 = 0ull;
            for (int i = 0; i < 32; i++) {
                c0 |= (unsigned long long)ivb[wp * 64 + i] << (2 * i);
                c1 |= (unsigned long long)ivb[wp * 64 + 32 + i] << (2 * i);
            }
            g_code[row * 2] = c0;
            g_code[row * 2 + 1] = c1;
        }
        __syncwarp();
    }
}

// ---------------- src scan + g_mem / H0 / C0 / read0 init --------------------
__device__ void stage_init(float* sm, const float* __restrict__ Mv0,
                           const float* __restrict__ hx0, const float* __restrict__ cx0,
                           int r0, int c0)
{
    float* wT = sm + OFF_WT;
    const int tid = threadIdx.x;
    if (tid < Tlen) {
        const int b = blockIdx.x, i = tid;
        unsigned long long cc0v = g_code[(b * Tlen + i) * 2];
        unsigned long long cc1v = g_code[(b * Tlen + i) * 2 + 1];
        int sv = i - 1;
        for (int j = i - 1; j >= 0; j--)
            if (g_code[(b * Tlen + j) * 2] == cc0v && g_code[(b * Tlen + j) * 2 + 1] == cc1v) { sv = j; break; }
        g_src[b * Tlen + i] = sv;
    }
    {
        int bl = tid >> 6, m = tid & 63;
        wT[tid] = g_w[((r0 + bl) * Tlen) * 64 + m];
    }
    // mem slice init: 16 rows x 64 m x 32 cc = 32768 elements
#pragma unroll
    for (int it = 0; it < 32; it++) {
        int i2 = tid + it * NTHR;
        int rr = i2 >> 11, rem = i2 & 2047;
        int m = rem >> 5, cc = rem & 31;
        g_mem[(((size_t)(r0 + rr)) * 64 + m) * Dm + c0 + cc] = Mv0[m * Dm + c0 + cc];
    }
    __syncthreads();
    if (tid < 512) {
        int rr = tid >> 5, cc = tid & 31;
        int b = r0 + rr, col = c0 + cc;
        g_H[(size_t)b * Dm + col] = hx0[col];
        g_C[(size_t)b * Dm + col] = cx0[col];
        float racc = 0.f;
#pragma unroll 4
        for (int m = 0; m < 64; m++)
            racc = fmaf(wT[rr * 64 + m], Mv0[m * Dm + col], racc);
        g_read[(size_t)b * Dm + col] = racc;
    }
}

// ---------------- f / we stage: C[16,32] = A[16,512] @ W[:, :512]^T + pre ----
template<int MODE>  // 0: A=g_read, W=Wf, out tanh -> g_f,g_ft ; 1: A=g_f, W=Wa -> g_we
__device__ void stage_fwe(float* sm, const float* __restrict__ W, int t, int r0, int c0)
{
    float* As = sm + OFF_AS;
    float* Ws = sm + OFF_WS;
    float* part = sm + OFF_PART;
    const int tid = threadIdx.x;
    const float* A = (MODE == 0) ? g_read : g_f;
#pragma unroll
    for (int h = 0; h < 2; h++) {
        int i = tid + h * NTHR;
        int rr = i & 15, kq = i >> 4;
        float4 v = *(const float4*)(A + (size_t)(r0 + rr) * Dm + kq * 4);
        float* a = As + (kq * 4) * 20 + rr;
        a[0] = v.x; a[20] = v.y; a[40] = v.z; a[60] = v.w;
    }
#pragma unroll
    for (int h = 0; h < 4; h++) {
        int i = tid + h * NTHR;
        int n = i & 31, kq = i >> 5;
        float4 v = *(const float4*)(W + (size_t)(c0 + n) * 1024 + kq * 4);
        float* w = Ws + (kq * 4) * 36 + n;
        w[0] = v.x; w[36] = v.y; w[72] = v.z; w[108] = v.w;
    }
    __syncthreads();
    const int s = tid >> 5, pos = tid & 31, rg = pos >> 3, cg = pos & 7;
    float acc[4][4] = {};
#pragma unroll
    for (int kk = 0; kk < 16; kk++) {
        int k = s * 16 + kk;
        float4 a4 = *(const float4*)(As + k * 20 + rg * 4);
        float4 w4 = *(const float4*)(Ws + k * 36 + cg * 4);
        fma16(acc, a4, w4);
    }
#pragma unroll
    for (int j = 0; j < 4; j++)
        *(float4*)(part + s * 576 + (rg * 4 + j) * 36 + cg * 4) =
            make_float4(acc[j][0], acc[j][1], acc[j][2], acc[j][3]);
    __syncthreads();
    if (tid < 512) {
        int rr = tid >> 5, cc = tid & 31;
        float v = 0.f;
#pragma unroll
        for (int p = 0; p < 32; p++) v += part[p * 576 + rr * 36 + cc];
        int b = r0 + rr, col = c0 + cc;
        if (MODE == 0) {
            v += g_preF[((size_t)b * Tlen + t) * Dm + col];
            v = tanhf(v);
            g_f[(size_t)b * Dm + col] = v;
            g_ft[((size_t)t * Bsz + b) * Dm + col] = v;
        } else {
            v += g_preWE[((size_t)b * Tlen + t) * Dm + col];
            g_we[(size_t)b * Dm + col] = v;
        }
    }
}

// ---------------- e/a GEMMs + memory update + fused read_{t+1} ----------------
__device__ void stage_ea(float* sm, const float* __restrict__ We, const float* __restrict__ be,
                         const float* __restrict__ Wadd, const float* __restrict__ badd,
                         int t, int r0, int c0)
{
    float* As = sm + OFF_AS;
    float* Ws = sm + OFF_WS;     // [256][72] per chunk: e cols [0,36), a cols [36,72)
    float* part = sm + OFF_PART;
    float* wT = sm + OFF_WT;
    float* wN = sm + OFF_WN;
    float* EA = sm + OFF_EA;
    float* RP = sm + OFF_RP;
    const int tid = threadIdx.x;
    {
        int bl = tid >> 6, m = tid & 63;
        wT[tid] = g_w[((r0 + bl) * Tlen + t) * 64 + m];
        wN[tid] = (t + 1 < Tlen) ? g_w[((r0 + bl) * Tlen + t + 1) * 64 + m] : 0.0f;
    }
#pragma unroll
    for (int h = 0; h < 2; h++) {
        int i = tid + h * NTHR;
        int rr = i & 15, kq = i >> 4;
        float4 v = *(const float4*)(g_we + (size_t)(r0 + rr) * Dm + kq * 4);
        float* a = As + (kq * 4) * 20 + rr;
        a[0] = v.x; a[20] = v.y; a[40] = v.z; a[60] = v.w;
    }
    const int hh = tid >> 9, sub = (tid >> 5) & 15, pos = tid & 31, rg = pos >> 3, cg = pos & 7;
    float acc[4][4] = {};
    for (int c2 = 0; c2 < 2; c2++) {
        const int kb = c2 * 256;
#pragma unroll
        for (int h = 0; h < 4; h++) {
            int i = tid + h * NTHR;
            int n2 = i & 63, kq = i >> 6;
            const float* Wp2 = (n2 < 32) ? We : Wadd;
            int n = (n2 < 32) ? n2 : n2 - 32;
            int wc = (n2 < 32) ? n2 : 36 + n2 - 32;
            float4 v = *(const float4*)(Wp2 + (size_t)(c0 + n) * Dm + kb + kq * 4);
            float* w = Ws + (kq * 4) * 72 + wc;
            w[0] = v.x; w[72] = v.y; w[144] = v.z; w[216] = v.w;
        }
        __syncthreads();
#pragma unroll
        for (int kk = 0; kk < 16; kk++) {
            int kl = sub * 16 + kk;
            float4 a4 = *(const float4*)(As + (kb + kl) * 20 + rg * 4);
            float4 w4 = *(const float4*)(Ws + kl * 72 + hh * 36 + cg * 4);
            fma16(acc, a4, w4);
        }
        __syncthreads();
    }
    const int slot = hh * 16 + sub;
#pragma unroll
    for (int j = 0; j < 4; j++)
        *(float4*)(part + slot * 576 + (rg * 4 + j) * 36 + cg * 4) =
            make_float4(acc[j][0], acc[j][1], acc[j][2], acc[j][3]);
    __syncthreads();
    if (tid < 512) {
        int rr = tid >> 5, cc = tid & 31;
        float ve = 0.f, va = 0.f;
#pragma unroll
        for (int p = 0; p < 16; p++)  ve += part[p * 576 + rr * 36 + cc];
#pragma unroll
        for (int p = 16; p < 32; p++) va += part[p * 576 + rr * 36 + cc];
        EA[tid] = sigm(ve + be[c0 + cc]);
        EA[512 + tid] = tanhf(va + badd[c0 + cc]);
    }
    __syncthreads();
    {
        int oid = tid & 511, mh = tid >> 9;
        int rr = oid >> 5, cc = oid & 31;
        float e = EA[oid], a = EA[512 + oid];
        float racc = 0.f;
        size_t base = ((size_t)(r0 + rr) * 64) * Dm + c0 + cc;
#pragma unroll 4
        for (int mi = 0; mi < 32; mi++) {
            int m = mh * 32 + mi;
            float wt = wT[rr * 64 + m], wn = wN[rr * 64 + m];
            float* p = g_mem + base + (size_t)m * Dm;
            float v = *p;
            v = v * (1.0f - wt * e) + wt * a;
            *p = v;
            racc = fmaf(wn, v, racc);
        }
        RP[tid] = racc;
    }
    __syncthreads();
    if (tid < 512) {
        int rr = tid >> 5, cc = tid & 31;
        g_read[(size_t)(r0 + rr) * Dm + c0 + cc] = RP[tid] + RP[512 + tid];
    }
}

// ---------------- parallel GEMM between loops: g_pre = ft @ Wih^T + biases ----
__device__ void stage_preG(float* sm, const float* __restrict__ Wih,
                           const float* __restrict__ bih, const float* __restrict__ bhh)
{
    float* As = sm + OFF_AS;   // [64][36]
    float* Ws = sm + OFF_WS;   // [32][68]
    const int tid = threadIdx.x;
    const int ty = tid >> 4, tx = tid & 15;
    for (int tile = blockIdx.x; tile < 3072; tile += NBLK) {
        const int row0 = (tile >> 5) * 64, cc0 = (tile & 31) * 64;
        float a0 = 0.f, a1 = 0.f, a2 = 0.f, a3 = 0.f;
        for (int ch = 0; ch < 16; ch++) {
            const int kb = ch * 32;
            if (tid < 512) {
                int rr = tid >> 3, kq = tid & 7;
                float4 v = *(const float4*)(g_ft + (size_t)(row0 + rr) * Dm + kb + kq * 4);
                *(float4*)(As + rr * 36 + kq * 4) = v;
            } else {
                int i = tid - 512;
                int n = i & 63, kq = i >> 6;
                float4 v = *(const float4*)(Wih + (size_t)(cc0 + n) * Dm + kb + kq * 4);
                float* w = Ws + (kq * 4) * 68 + n;
                w[0] = v.x; w[68] = v.y; w[136] = v.z; w[204] = v.w;
            }
            __syncthreads();
#pragma unroll
            for (int c = 0; c < 32; c++) {
                float a = As[ty * 36 + c];
                float4 w4 = *(const float4*)(Ws + c * 68 + tx * 4);
                a0 = fmaf(a, w4.x, a0); a1 = fmaf(a, w4.y, a1);
                a2 = fmaf(a, w4.z, a2); a3 = fmaf(a, w4.w, a3);
            }
            __syncthreads();
        }
        const int row = row0 + ty, col = cc0 + tx * 4;
        *(float4*)(g_pre + (size_t)row * 2048 + col) =
            make_float4(a0 + bih[col] + bhh[col],     a1 + bih[col+1] + bhh[col+1],
                        a2 + bih[col+2] + bhh[col+2], a3 + bih[col+3] + bhh[col+3]);
    }
}

// ---------------- hop-LSTM step: gates = h_src @ Whh^T + g_pre ----------------
__device__ void stage_lstm(float* sm, const float* __restrict__ Whh, int t, int r0, int c0)
{
    float* As = sm + OFF_AS;
    float* Ws = sm + OFF_WS;   // [128][144] per chunk: gate g cols at [k][g*36 + n]
    float* part = sm + OFF_PART;
    int* s16 = (int*)(sm + OFF_I64);
    const int tid = threadIdx.x;
    if (tid < 16) s16[tid] = g_src[(r0 + tid) * Tlen + t] + 1;
    __syncthreads();
#pragma unroll
    for (int h = 0; h < 2; h++) {
        int i = tid + h * NTHR;
        int rr = i & 15, kq = i >> 4;
        float4 v = *(const float4*)(g_H + ((size_t)s16[rr] * Bsz + r0 + rr) * Dm + kq * 4);
        float* a = As + (kq * 4) * 20 + rr;
        a[0] = v.x; a[20] = v.y; a[40] = v.z; a[60] = v.w;
    }
    const int gate = tid >> 8, sub = (tid >> 5) & 7, pos = tid & 31, rg = pos >> 3, cg = pos & 7;
    float acc[4][4] = {};
    for (int c4 = 0; c4 < 4; c4++) {
        const int kb = c4 * 128;
#pragma unroll
        for (int h = 0; h < 4; h++) {
            int i = tid + h * NTHR;
            int col = i & 127, kq = i >> 7;
            int g2 = col >> 5, n = col & 31;
            float4 v = *(const float4*)(Whh + (size_t)(g2 * Dm + c0 + n) * Dm + kb + kq * 4);
            float* w = Ws + (kq * 4) * 144 + g2 * 36 + n;
            w[0] = v.x; w[144] = v.y; w[288] = v.z; w[432] = v.w;
        }
        __syncthreads();
#pragma unroll
        for (int kk = 0; kk < 16; kk++) {
            int kl = sub * 16 + kk;
            float4 a4 = *(const float4*)(As + (kb + kl) * 20 + rg * 4);
            float4 w4 = *(const float4*)(Ws + kl * 144 + gate * 36 + cg * 4);
            fma16(acc, a4, w4);
        }
        __syncthreads();
    }
    const int slot = gate * 8 + sub;
#pragma unroll
    for (int j = 0; j < 4; j++)
        *(float4*)(part + slot * 576 + (rg * 4 + j) * 36 + cg * 4) =
            make_float4(acc[j][0], acc[j][1], acc[j][2], acc[j][3]);
    __syncthreads();
    if (tid < 512) {
        int rr = tid >> 5, cc = tid & 31;
        float gs[4];
#pragma unroll
        for (int g2 = 0; g2 < 4; g2++) {
            float v = 0.f;
#pragma unroll
            for (int p = g2 * 8; p < g2 * 8 + 8; p++) v += part[p * 576 + rr * 36 + cc];
            gs[g2] = v;
        }
        const int b = r0 + rr, col = c0 + cc;
        const float* pre = g_pre + ((size_t)t * Bsz + b) * 2048;
        float gi = gs[0] + pre[col];
        float gf = gs[1] + pre[512 + col];
        float gg = gs[2] + pre[1024 + col];
        float go = gs[3] + pre[1536 + col];
        float cin = g_C[((size_t)s16[rr] * Bsz + b) * Dm + col];
        float cn = sigm(gf) * cin + sigm(gi) * tanhf(gg);
        float hn = sigm(go) * tanhf(cn);
        g_C[((size_t)(t + 1) * Bsz + b) * Dm + col] = cn;
        g_H[((size_t)(t + 1) * Bsz + b) * Dm + col] = hn;
    }
}

// ---------------- prediction head ---------------------------------------------
__device__ void stage_head(const float* __restrict__ Wp, const float* __restrict__ bp,
                           float* __restrict__ out)
{
    const int wp = threadIdx.x >> 5, lane = threadIdx.x & 31;
    for (int bt = blockIdx.x * 32 + wp; bt < Bsz * Tlen; bt += NBLK * 32) {
        const int b = bt / Tlen, t = bt % Tlen;
        const float* h = &g_H[((size_t)(t + 1) * Bsz + b) * Dm];
        float s = 0.f;
        for (int i = lane; i < Dm; i += 32) s = fmaf(h[i], Wp[i], s);
        for (int o = 16; o; o >>= 1) s += __shfl_xor_sync(0xffffffffu, s, o);
        if (lane == 0) out[bt] = sigm(s + bp[0]);
    }
}

// ---------------- the single persistent kernel --------------------------------
__global__ void __launch_bounds__(NTHR, 1) k_persist(
    const int* __restrict__ q, const int* __restrict__ r,
    const float* __restrict__ Mk, const float* __restrict__ Mv0,
    const float* __restrict__ ktab, const float* __restrict__ xtab,
    const float* __restrict__ We, const float* __restrict__ be,
    const float* __restrict__ Wadd, const float* __restrict__ badd,
    const float* __restrict__ Wa, const float* __restrict__ ba,
    const float* __restrict__ Wf, const float* __restrict__ bf,
    const float* __restrict__ Wih, const float* __restrict__ Whh,
    const float* __restrict__ bih, const float* __restrict__ bhh,
    const float* __restrict__ hx0, const float* __restrict__ cx0,
    const float* __restrict__ Wp, const float* __restrict__ bp,
    float* __restrict__ out)
{
    extern __shared__ float sm[];
    unsigned ls = 0;
    if (threadIdx.x == 0) ls = g_sense;
    const int r0 = (blockIdx.x & 7) * 16;
    const int c0 = (blockIdx.x >> 3) * 32;

    stage_par(sm, ktab, xtab, q, r, Wf, bf, Wa, ba, Mk);   gsync(ls);
    stage_softmax(sm);                                     gsync(ls);
    stage_init(sm, Mv0, hx0, cx0, r0, c0);                 gsync(ls);

    for (int t = 0; t < Tlen; t++) {
        stage_fwe<0>(sm, Wf, t, r0, c0);                   gsync(ls);
        stage_fwe<1>(sm, Wa, t, r0, c0);                   gsync(ls);
        stage_ea(sm, We, be, Wadd, badd, t, r0, c0);       gsync(ls);
    }
    stage_preG(sm, Wih, bih, bhh);                         gsync(ls);
    for (int t = 0; t < Tlen; t++) {
        stage_lstm(sm, Whh, t, r0, c0);                    gsync(ls);
    }
    stage_head(Wp, bp, out);
}

// ----------------------------------------------------------------------------
extern "C" void kernel_launch(void* const* d_in, const int* in_sizes, int n_in,
                              void* d_out, int out_size)
{
    const int*   q    = (const int*)d_in[0];
    const int*   r    = (const int*)d_in[1];
    const float* Mk   = (const float*)d_in[2];
    const float* Mv0  = (const float*)d_in[3];
    const float* ktab = (const float*)d_in[4];
    const float* xtab = (const float*)d_in[5];
    const float* We   = (const float*)d_in[6];
    const float* be   = (const float*)d_in[7];
    const float* Wadd = (const float*)d_in[8];
    const float* badd = (const float*)d_in[9];
    const float* Wa   = (const float*)d_in[10];
    const float* ba   = (const float*)d_in[11];
    const float* Wf   = (const float*)d_in[12];
    const float* bf   = (const float*)d_in[13];
    const float* Wih  = (const float*)d_in[14];
    const float* Whh  = (const float*)d_in[15];
    const float* bih  = (const float*)d_in[16];
    const float* bhh  = (const float*)d_in[17];
    const float* hx0  = (const float*)d_in[18];
    const float* cx0  = (const float*)d_in[19];
    const float* Wp   = (const float*)d_in[20];
    const float* bp   = (const float*)d_in[21];
    float* out = (float*)d_out;

    static bool attr_set = false;
    if (!attr_set) {
        cudaFuncSetAttribute(k_persist, cudaFuncAttributeMaxDynamicSharedMemorySize, SMEM_BYTES);
        attr_set = true;
    }
    k_persist<<<NBLK, NTHR, SMEM_BYTES>>>(q, r, Mk, Mv0, ktab, xtab, We, be, Wadd, badd,
                                          Wa, ba, Wf, bf, Wih, Whh, bih, bhh,
                                          hx0, cx0, Wp, bp, out);
}

// round 6
// speedup vs baseline: 1.0011x; 1.0008x over previous
#include <cuda_runtime.h>
#include <math.h>

#define Bsz 128
#define Tlen 48
#define Dm 512
#define NBLK 128
#define NTHR 1024

// ---------------- global scratch ---------------------------------------------
__device__ float g_w[Bsz*Tlen*64];
__device__ unsigned long long g_code[Bsz*Tlen*2];
__device__ int g_src[Bsz*Tlen];
__device__ float g_mem[Bsz*64*Dm];
__device__ float g_read[Bsz*Dm];
__device__ float g_f[Bsz*Dm];
__device__ float g_we[Bsz*Dm];
__device__ float g_ft[Tlen*Bsz*Dm];
__device__ float g_preF[Bsz*Tlen*Dm];     // k_emb @ WfR^T + bf   (rows b*T+t)
__device__ float g_preWE[Bsz*Tlen*Dm];    // y_emb @ WaR^T + ba   (rows b*T+t)
__device__ float g_pre[Tlen*Bsz*2048];    // ft @ Wih^T + bih + bhh (rows t*B+b)
__device__ float g_H[(Tlen+1)*Bsz*Dm];
__device__ float g_C[(Tlen+1)*Bsz*Dm];
__device__ unsigned g_count = 0;
__device__ volatile unsigned g_sense = 0;

__device__ __forceinline__ float sigm(float x) { return 1.0f / (1.0f + expf(-x)); }

// ---------------- smem layout (floats) ----------------------------------------
#define OFF_AS   0        // 512 x 20 (k-major A, 16 rows)  = 10240
#define OFF_WS   10240    // 18432: [512][36] fwe | [256][72] ea | [128][144] lstm | par/preG slices
#define OFF_PART 28672    // 32 x 16 x 36 = 18432
#define OFF_WT   47104    // 1024
#define OFF_WN   48128    // 1024
#define OFF_EA   49152    // 1024 (also softmax ivb bytes)
#define OFF_RP   50176    // 1024
#define OFF_I64  51200    // 64 ints
#define SMEM_FLOATS 51264
#define SMEM_BYTES (SMEM_FLOATS * 4)

// ---------------- grid-wide barrier -------------------------------------------
__device__ __forceinline__ void gsync(unsigned& ls) {
    __syncthreads();
    if (threadIdx.x == 0) {
        unsigned target = ls ^ 1u;
        __threadfence();
        if (atomicAdd(&g_count, 1u) == gridDim.x - 1) {
            atomicExch(&g_count, 0u);
            __threadfence();
            g_sense = target;
        } else {
            while (g_sense != target) { }
        }
        ls = target;
        __threadfence();
    }
    __syncthreads();
}

__device__ __forceinline__ void fma16(float (&acc)[4][4], float4 a, float4 w) {
    acc[0][0]=fmaf(a.x,w.x,acc[0][0]); acc[0][1]=fmaf(a.x,w.y,acc[0][1]);
    acc[0][2]=fmaf(a.x,w.z,acc[0][2]); acc[0][3]=fmaf(a.x,w.w,acc[0][3]);
    acc[1][0]=fmaf(a.y,w.x,acc[1][0]); acc[1][1]=fmaf(a.y,w.y,acc[1][1]);
    acc[1][2]=fmaf(a.y,w.z,acc[1][2]); acc[1][3]=fmaf(a.y,w.w,acc[1][3]);
    acc[2][0]=fmaf(a.z,w.x,acc[2][0]); acc[2][1]=fmaf(a.z,w.y,acc[2][1]);
    acc[2][2]=fmaf(a.z,w.z,acc[2][2]); acc[2][3]=fmaf(a.z,w.w,acc[2][3]);
    acc[3][0]=fmaf(a.w,w.x,acc[3][0]); acc[3][1]=fmaf(a.w,w.y,acc[3][1]);
    acc[3][2]=fmaf(a.w,w.z,acc[3][2]); acc[3][3]=fmaf(a.w,w.w,acc[3][3]);
}

// ---------------- upfront parallel GEMMs: preF, preWE, addr -------------------
// tiles 64x64 (addr: 64x64 with N=64): A = gathered table rows, C = A @ W^T
__device__ void stage_par(float* sm,
                          const float* __restrict__ ktab, const float* __restrict__ xtab,
                          const int* __restrict__ q, const int* __restrict__ r,
                          const float* __restrict__ Wf, const float* __restrict__ bf,
                          const float* __restrict__ Wa, const float* __restrict__ ba,
                          const float* __restrict__ Mk)
{
    float* As = sm + OFF_AS;   // [64][36] row-major (k-local in row)
    float* Ws = sm + OFF_WS;   // [32][68]
    int* sIdx = (int*)(sm + OFF_I64);
    const int tid = threadIdx.x;
    const int ty = tid >> 4, tx = tid & 15;
    for (int tile = blockIdx.x; tile < 1632; tile += NBLK) {
        int seg, row0, cc0;
        if (tile < 768)       { seg = 0; row0 = (tile >> 3) * 64; cc0 = (tile & 7) * 64; }
        else if (tile < 1536) { int tl = tile - 768;  seg = 1; row0 = (tl >> 3) * 64; cc0 = (tl & 7) * 64; }
        else                  { int tl = tile - 1536; seg = 2; row0 = tl * 64; cc0 = 0; }
        if (tid < 64) {
            int rid = row0 + tid;
            int qi = q[rid];
            sIdx[tid] = (seg == 1) ? (qi + 2000 * r[rid]) : qi;
        }
        __syncthreads();
        float a0 = 0.f, a1 = 0.f, a2 = 0.f, a3 = 0.f;
        for (int ch = 0; ch < 16; ch++) {
            const int kb = ch * 32;
            if (tid < 512) {
                int rr = tid >> 3, kq = tid & 7;
                const float* tab = (seg == 1) ? xtab : ktab;
                float4 v = *(const float4*)(tab + (size_t)sIdx[rr] * Dm + kb + kq * 4);
                *(float4*)(As + rr * 36 + kq * 4) = v;
            } else {
                int i = tid - 512;
                int n = i & 63, kq = i >> 6;
                float4 v;
                if (seg == 0)      v = *(const float4*)(Wf + (size_t)(cc0 + n) * 1024 + 512 + kb + kq * 4);
                else if (seg == 1) v = *(const float4*)(Wa + (size_t)(cc0 + n) * 1024 + 512 + kb + kq * 4);
                else               v = *(const float4*)(Mk + (size_t)(cc0 + n) * 512 + kb + kq * 4);
                float* w = Ws + (kq * 4) * 68 + n;
                w[0] = v.x; w[68] = v.y; w[136] = v.z; w[204] = v.w;
            }
            __syncthreads();
#pragma unroll
            for (int c = 0; c < 32; c++) {
                float a = As[ty * 36 + c];
                float4 w4 = *(const float4*)(Ws + c * 68 + tx * 4);
                a0 = fmaf(a, w4.x, a0); a1 = fmaf(a, w4.y, a1);
                a2 = fmaf(a, w4.z, a2); a3 = fmaf(a, w4.w, a3);
            }
            __syncthreads();
        }
        const int row = row0 + ty, col = cc0 + tx * 4;
        if (seg == 0) {
            *(float4*)(g_preF + (size_t)row * Dm + col) =
                make_float4(a0 + bf[col], a1 + bf[col+1], a2 + bf[col+2], a3 + bf[col+3]);
        } else if (seg == 1) {
            *(float4*)(g_preWE + (size_t)row * Dm + col) =
                make_float4(a0 + ba[col], a1 + ba[col+1], a2 + ba[col+2], a3 + ba[col+3]);
        } else {
            *(float4*)(g_w + (size_t)row * 64 + col) = make_float4(a0, a1, a2, a3);
        }
    }
}

// ---------------- softmax + membership codes ----------------------------------
__device__ void stage_softmax(float* sm)
{
    unsigned char* ivb = (unsigned char*)(sm + OFF_EA);   // [32][64]
    const int wp = threadIdx.x >> 5, lane = threadIdx.x & 31;
    for (int rr = wp; rr < 48; rr += 32) {
        const int row = blockIdx.x * 48 + rr;
        float v0 = g_w[row * 64 + lane];
        float v1 = g_w[row * 64 + 32 + lane];
        float mx = fmaxf(v0, v1);
        for (int o = 16; o; o >>= 1) mx = fmaxf(mx, __shfl_xor_sync(0xffffffffu, mx, o));
        float e0 = expf(v0 - mx), e1 = expf(v1 - mx);
        float ss = e0 + e1;
        for (int o = 16; o; o >>= 1) ss += __shfl_xor_sync(0xffffffffu, ss, o);
        float inv = 1.0f / ss;
        float w0 = e0 * inv, w1 = e1 * inv;
        g_w[row * 64 + lane] = w0;
        g_w[row * 64 + 32 + lane] = w1;
        auto ivf = [](float w) -> int {
            float m = fmaxf(fminf((w - 0.075f) / (0.088f - 0.075f),
                                  (1.0f - w) / (1.0f - 0.088f)), 0.0f);
            return (m >= 0.6f) ? 2 : ((m >= 0.1f) ? 1 : 0);
        };
        ivb[wp * 64 + lane] = (unsigned char)ivf(w0);
        ivb[wp * 64 + 32 + lane] = (unsigned char)ivf(w1);
        __syncwarp();
        if (lane == 0) {
            unsigned long long c0 = 0ull, c1 = 0ull;
            for (int i = 0; i < 32; i++) {
                c0 |= (unsigned long long)ivb[wp * 64 + i] << (2 * i);
                c1 |= (unsigned long long)ivb[wp * 64 + 32 + i] << (2 * i);
            }
            g_code[row * 2] = c0;
            g_code[row * 2 + 1] = c1;
        }
        __syncwarp();
    }
}

// ---------------- src scan + g_mem / H0 / C0 / read0 init --------------------
__device__ void stage_init(float* sm, const float* __restrict__ Mv0,
                           const float* __restrict__ hx0, const float* __restrict__ cx0,
                           int r0, int c0)
{
    float* wT = sm + OFF_WT;
    const int tid = threadIdx.x;
    if (tid < Tlen) {
        const int b = blockIdx.x, i = tid;
        unsigned long long cc0v = g_code[(b * Tlen + i) * 2];
        unsigned long long cc1v = g_code[(b * Tlen + i) * 2 + 1];
        int sv = i - 1;
        for (int j = i - 1; j >= 0; j--)
            if (g_code[(b * Tlen + j) * 2] == cc0v && g_code[(b * Tlen + j) * 2 + 1] == cc1v) { sv = j; break; }
        g_src[b * Tlen + i] = sv;
    }
    {
        int bl = tid >> 6, m = tid & 63;
        wT[tid] = g_w[((r0 + bl) * Tlen) * 64 + m];
    }
    // mem slice init: 16 rows x 64 m x 32 cc = 32768 elements
#pragma unroll
    for (int it = 0; it < 32; it++) {
        int i2 = tid + it * NTHR;
        int rr = i2 >> 11, rem = i2 & 2047;
        int m = rem >> 5, cc = rem & 31;
        g_mem[(((size_t)(r0 + rr)) * 64 + m) * Dm + c0 + cc] = Mv0[m * Dm + c0 + cc];
    }
    __syncthreads();
    if (tid < 512) {
        int rr = tid >> 5, cc = tid & 31;
        int b = r0 + rr, col = c0 + cc;
        g_H[(size_t)b * Dm + col] = hx0[col];
        g_C[(size_t)b * Dm + col] = cx0[col];
        float racc = 0.f;
#pragma unroll 4
        for (int m = 0; m < 64; m++)
            racc = fmaf(wT[rr * 64 + m], Mv0[m * Dm + col], racc);
        g_read[(size_t)b * Dm + col] = racc;
    }
}

// ---------------- f / we stage: C[16,32] = A[16,512] @ W[:, :512]^T + pre ----
template<int MODE>  // 0: A=g_read, W=Wf, out tanh -> g_f,g_ft ; 1: A=g_f, W=Wa -> g_we
__device__ void stage_fwe(float* sm, const float* __restrict__ W, int t, int r0, int c0)
{
    float* As = sm + OFF_AS;
    float* Ws = sm + OFF_WS;
    float* part = sm + OFF_PART;
    const int tid = threadIdx.x;
    const float* A = (MODE == 0) ? g_read : g_f;
#pragma unroll
    for (int h = 0; h < 2; h++) {
        int i = tid + h * NTHR;
        int rr = i & 15, kq = i >> 4;
        float4 v = *(const float4*)(A + (size_t)(r0 + rr) * Dm + kq * 4);
        float* a = As + (kq * 4) * 20 + rr;
        a[0] = v.x; a[20] = v.y; a[40] = v.z; a[60] = v.w;
    }
#pragma unroll
    for (int h = 0; h < 4; h++) {
        int i = tid + h * NTHR;
        int n = i & 31, kq = i >> 5;
        float4 v = *(const float4*)(W + (size_t)(c0 + n) * 1024 + kq * 4);
        float* w = Ws + (kq * 4) * 36 + n;
        w[0] = v.x; w[36] = v.y; w[72] = v.z; w[108] = v.w;
    }
    __syncthreads();
    const int s = tid >> 5, pos = tid & 31, rg = pos >> 3, cg = pos & 7;
    float acc[4][4] = {};
#pragma unroll
    for (int kk = 0; kk < 16; kk++) {
        int k = s * 16 + kk;
        float4 a4 = *(const float4*)(As + k * 20 + rg * 4);
        float4 w4 = *(const float4*)(Ws + k * 36 + cg * 4);
        fma16(acc, a4, w4);
    }
#pragma unroll
    for (int j = 0; j < 4; j++)
        *(float4*)(part + s * 576 + (rg * 4 + j) * 36 + cg * 4) =
            make_float4(acc[j][0], acc[j][1], acc[j][2], acc[j][3]);
    __syncthreads();
    if (tid < 512) {
        int rr = tid >> 5, cc = tid & 31;
        float v = 0.f;
#pragma unroll
        for (int p = 0; p < 32; p++) v += part[p * 576 + rr * 36 + cc];
        int b = r0 + rr, col = c0 + cc;
        if (MODE == 0) {
            v += g_preF[((size_t)b * Tlen + t) * Dm + col];
            v = tanhf(v);
            g_f[(size_t)b * Dm + col] = v;
            g_ft[((size_t)t * Bsz + b) * Dm + col] = v;
        } else {
            v += g_preWE[((size_t)b * Tlen + t) * Dm + col];
            g_we[(size_t)b * Dm + col] = v;
        }
    }
}

// ---------------- e/a GEMMs + memory update + fused read_{t+1} ----------------
__device__ void stage_ea(float* sm, const float* __restrict__ We, const float* __restrict__ be,
                         const float* __restrict__ Wadd, const float* __restrict__ badd,
                         int t, int r0, int c0)
{
    float* As = sm + OFF_AS;
    float* Ws = sm + OFF_WS;     // [256][72] per chunk: e cols [0,36), a cols [36,72)
    float* part = sm + OFF_PART;
    float* wT = sm + OFF_WT;
    float* wN = sm + OFF_WN;
    float* EA = sm + OFF_EA;
    float* RP = sm + OFF_RP;
    const int tid = threadIdx.x;
    {
        int bl = tid >> 6, m = tid & 63;
        wT[tid] = g_w[((r0 + bl) * Tlen + t) * 64 + m];
        wN[tid] = (t + 1 < Tlen) ? g_w[((r0 + bl) * Tlen + t + 1) * 64 + m] : 0.0f;
    }
#pragma unroll
    for (int h = 0; h < 2; h++) {
        int i = tid + h * NTHR;
        int rr = i & 15, kq = i >> 4;
        float4 v = *(const float4*)(g_we + (size_t)(r0 + rr) * Dm + kq * 4);
        float* a = As + (kq * 4) * 20 + rr;
        a[0] = v.x; a[20] = v.y; a[40] = v.z; a[60] = v.w;
    }
    const int hh = tid >> 9, sub = (tid >> 5) & 15, pos = tid & 31, rg = pos >> 3, cg = pos & 7;
    float acc[4][4] = {};
    for (int c2 = 0; c2 < 2; c2++) {
        const int kb = c2 * 256;
#pragma unroll
        for (int h = 0; h < 4; h++) {
            int i = tid + h * NTHR;
            int n2 = i & 63, kq = i >> 6;
            const float* Wp2 = (n2 < 32) ? We : Wadd;
            int n = (n2 < 32) ? n2 : n2 - 32;
            int wc = (n2 < 32) ? n2 : 36 + n2 - 32;
            float4 v = *(const float4*)(Wp2 + (size_t)(c0 + n) * Dm + kb + kq * 4);
            float* w = Ws + (kq * 4) * 72 + wc;
            w[0] = v.x; w[72] = v.y; w[144] = v.z; w[216] = v.w;
        }
        __syncthreads();
#pragma unroll
        for (int kk = 0; kk < 16; kk++) {
            int kl = sub * 16 + kk;
            float4 a4 = *(const float4*)(As + (kb + kl) * 20 + rg * 4);
            float4 w4 = *(const float4*)(Ws + kl * 72 + hh * 36 + cg * 4);
            fma16(acc, a4, w4);
        }
        __syncthreads();
    }
    const int slot = hh * 16 + sub;
#pragma unroll
    for (int j = 0; j < 4; j++)
        *(float4*)(part + slot * 576 + (rg * 4 + j) * 36 + cg * 4) =
            make_float4(acc[j][0], acc[j][1], acc[j][2], acc[j][3]);
    __syncthreads();
    if (tid < 512) {
        int rr = tid >> 5, cc = tid & 31;
        float ve = 0.f, va = 0.f;
#pragma unroll
        for (int p = 0; p < 16; p++)  ve += part[p * 576 + rr * 36 + cc];
#pragma unroll
        for (int p = 16; p < 32; p++) va += part[p * 576 + rr * 36 + cc];
        EA[tid] = sigm(ve + be[c0 + cc]);
        EA[512 + tid] = tanhf(va + badd[c0 + cc]);
    }
    __syncthreads();
    {
        int oid = tid & 511, mh = tid >> 9;
        int rr = oid >> 5, cc = oid & 31;
        float e = EA[oid], a = EA[512 + oid];
        float racc = 0.f;
        size_t base = ((size_t)(r0 + rr) * 64) * Dm + c0 + cc;
#pragma unroll 4
        for (int mi = 0; mi < 32; mi++) {
            int m = mh * 32 + mi;
            float wt = wT[rr * 64 + m], wn = wN[rr * 64 + m];
            float* p = g_mem + base + (size_t)m * Dm;
            float v = *p;
            v = v * (1.0f - wt * e) + wt * a;
            *p = v;
            racc = fmaf(wn, v, racc);
        }
        RP[tid] = racc;
    }
    __syncthreads();
    if (tid < 512) {
        int rr = tid >> 5, cc = tid & 31;
        g_read[(size_t)(r0 + rr) * Dm + c0 + cc] = RP[tid] + RP[512 + tid];
    }
}

// ---------------- parallel GEMM between loops: g_pre = ft @ Wih^T + biases ----
__device__ void stage_preG(float* sm, const float* __restrict__ Wih,
                           const float* __restrict__ bih, const float* __restrict__ bhh)
{
    float* As = sm + OFF_AS;   // [64][36]
    float* Ws = sm + OFF_WS;   // [32][68]
    const int tid = threadIdx.x;
    const int ty = tid >> 4, tx = tid & 15;
    for (int tile = blockIdx.x; tile < 3072; tile += NBLK) {
        const int row0 = (tile >> 5) * 64, cc0 = (tile & 31) * 64;
        float a0 = 0.f, a1 = 0.f, a2 = 0.f, a3 = 0.f;
        for (int ch = 0; ch < 16; ch++) {
            const int kb = ch * 32;
            if (tid < 512) {
                int rr = tid >> 3, kq = tid & 7;
                float4 v = *(const float4*)(g_ft + (size_t)(row0 + rr) * Dm + kb + kq * 4);
                *(float4*)(As + rr * 36 + kq * 4) = v;
            } else {
                int i = tid - 512;
                int n = i & 63, kq = i >> 6;
                float4 v = *(const float4*)(Wih + (size_t)(cc0 + n) * Dm + kb + kq * 4);
                float* w = Ws + (kq * 4) * 68 + n;
                w[0] = v.x; w[68] = v.y; w[136] = v.z; w[204] = v.w;
            }
            __syncthreads();
#pragma unroll
            for (int c = 0; c < 32; c++) {
                float a = As[ty * 36 + c];
                float4 w4 = *(const float4*)(Ws + c * 68 + tx * 4);
                a0 = fmaf(a, w4.x, a0); a1 = fmaf(a, w4.y, a1);
                a2 = fmaf(a, w4.z, a2); a3 = fmaf(a, w4.w, a3);
            }
            __syncthreads();
        }
        const int row = row0 + ty, col = cc0 + tx * 4;
        *(float4*)(g_pre + (size_t)row * 2048 + col) =
            make_float4(a0 + bih[col] + bhh[col],     a1 + bih[col+1] + bhh[col+1],
                        a2 + bih[col+2] + bhh[col+2], a3 + bih[col+3] + bhh[col+3]);
    }
}

// ---------------- hop-LSTM step: gates = h_src @ Whh^T + g_pre ----------------
__device__ void stage_lstm(float* sm, const float* __restrict__ Whh, int t, int r0, int c0)
{
    float* As = sm + OFF_AS;
    float* Ws = sm + OFF_WS;   // [128][144] per chunk: gate g cols at [k][g*36 + n]
    float* part = sm + OFF_PART;
    int* s16 = (int*)(sm + OFF_I64);
    const int tid = threadIdx.x;
    if (tid < 16) s16[tid] = g_src[(r0 + tid) * Tlen + t] + 1;
    __syncthreads();
#pragma unroll
    for (int h = 0; h < 2; h++) {
        int i = tid + h * NTHR;
        int rr = i & 15, kq = i >> 4;
        float4 v = *(const float4*)(g_H + ((size_t)s16[rr] * Bsz + r0 + rr) * Dm + kq * 4);
        float* a = As + (kq * 4) * 20 + rr;
        a[0] = v.x; a[20] = v.y; a[40] = v.z; a[60] = v.w;
    }
    const int gate = tid >> 8, sub = (tid >> 5) & 7, pos = tid & 31, rg = pos >> 3, cg = pos & 7;
    float acc[4][4] = {};
    for (int c4 = 0; c4 < 4; c4++) {
        const int kb = c4 * 128;
#pragma unroll
        for (int h = 0; h < 4; h++) {
            int i = tid + h * NTHR;
            int col = i & 127, kq = i >> 7;
            int g2 = col >> 5, n = col & 31;
            float4 v = *(const float4*)(Whh + (size_t)(g2 * Dm + c0 + n) * Dm + kb + kq * 4);
            float* w = Ws + (kq * 4) * 144 + g2 * 36 + n;
            w[0] = v.x; w[144] = v.y; w[288] = v.z; w[432] = v.w;
        }
        __syncthreads();
#pragma unroll
        for (int kk = 0; kk < 16; kk++) {
            int kl = sub * 16 + kk;
            float4 a4 = *(const float4*)(As + (kb + kl) * 20 + rg * 4);
            float4 w4 = *(const float4*)(Ws + kl * 144 + gate * 36 + cg * 4);
            fma16(acc, a4, w4);
        }
        __syncthreads();
    }
    const int slot = gate * 8 + sub;
#pragma unroll
    for (int j = 0; j < 4; j++)
        *(float4*)(part + slot * 576 + (rg * 4 + j) * 36 + cg * 4) =
            make_float4(acc[j][0], acc[j][1], acc[j][2], acc[j][3]);
    __syncthreads();
    if (tid < 512) {
        int rr = tid >> 5, cc = tid & 31;
        float gs[4];
#pragma unroll
        for (int g2 = 0; g2 < 4; g2++) {
            float v = 0.f;
#pragma unroll
            for (int p = g2 * 8; p < g2 * 8 + 8; p++) v += part[p * 576 + rr * 36 + cc];
            gs[g2] = v;
        }
        const int b = r0 + rr, col = c0 + cc;
        const float* pre = g_pre + ((size_t)t * Bsz + b) * 2048;
        float gi = gs[0] + pre[col];
        float gf = gs[1] + pre[512 + col];
        float gg = gs[2] + pre[1024 + col];
        float go = gs[3] + pre[1536 + col];
        float cin = g_C[((size_t)s16[rr] * Bsz + b) * Dm + col];
        float cn = sigm(gf) * cin + sigm(gi) * tanhf(gg);
        float hn = sigm(go) * tanhf(cn);
        g_C[((size_t)(t + 1) * Bsz + b) * Dm + col] = cn;
        g_H[((size_t)(t + 1) * Bsz + b) * Dm + col] = hn;
    }
}

// ---------------- prediction head ---------------------------------------------
__device__ void stage_head(const float* __restrict__ Wp, const float* __restrict__ bp,
                           float* __restrict__ out)
{
    const int wp = threadIdx.x >> 5, lane = threadIdx.x & 31;
    for (int bt = blockIdx.x * 32 + wp; bt < Bsz * Tlen; bt += NBLK * 32) {
        const int b = bt / Tlen, t = bt % Tlen;
        const float* h = &g_H[((size_t)(t + 1) * Bsz + b) * Dm];
        float s = 0.f;
        for (int i = lane; i < Dm; i += 32) s = fmaf(h[i], Wp[i], s);
        for (int o = 16; o; o >>= 1) s += __shfl_xor_sync(0xffffffffu, s, o);
        if (lane == 0) out[bt] = sigm(s + bp[0]);
    }
}

// ---------------- the single persistent kernel --------------------------------
__global__ void __launch_bounds__(NTHR, 1) k_persist(
    const int* __restrict__ q, const int* __restrict__ r,
    const float* __restrict__ Mk, const float* __restrict__ Mv0,
    const float* __restrict__ ktab, const float* __restrict__ xtab,
    const float* __restrict__ We, const float* __restrict__ be,
    const float* __restrict__ Wadd, const float* __restrict__ badd,
    const float* __restrict__ Wa, const float* __restrict__ ba,
    const float* __restrict__ Wf, const float* __restrict__ bf,
    const float* __restrict__ Wih, const float* __restrict__ Whh,
    const float* __restrict__ bih, const float* __restrict__ bhh,
    const float* __restrict__ hx0, const float* __restrict__ cx0,
    const float* __restrict__ Wp, const float* __restrict__ bp,
    float* __restrict__ out)
{
    extern __shared__ float sm[];
    unsigned ls = 0;
    if (threadIdx.x == 0) ls = g_sense;
    const int r0 = (blockIdx.x & 7) * 16;
    const int c0 = (blockIdx.x >> 3) * 32;

    stage_par(sm, ktab, xtab, q, r, Wf, bf, Wa, ba, Mk);   gsync(ls);
    stage_softmax(sm);                                     gsync(ls);
    stage_init(sm, Mv0, hx0, cx0, r0, c0);                 gsync(ls);

    for (int t = 0; t < Tlen; t++) {
        stage_fwe<0>(sm, Wf, t, r0, c0);                   gsync(ls);
        stage_fwe<1>(sm, Wa, t, r0, c0);                   gsync(ls);
        stage_ea(sm, We, be, Wadd, badd, t, r0, c0);       gsync(ls);
    }
    stage_preG(sm, Wih, bih, bhh);                         gsync(ls);
    for (int t = 0; t < Tlen; t++) {
        stage_lstm(sm, Whh, t, r0, c0);                    gsync(ls);
    }
    stage_head(Wp, bp, out);
}

// ----------------------------------------------------------------------------
extern "C" void kernel_launch(void* const* d_in, const int* in_sizes, int n_in,
                              void* d_out, int out_size)
{
    const int*   q    = (const int*)d_in[0];
    const int*   r    = (const int*)d_in[1];
    const float* Mk   = (const float*)d_in[2];
    const float* Mv0  = (const float*)d_in[3];
    const float* ktab = (const float*)d_in[4];
    const float* xtab = (const float*)d_in[5];
    const float* We   = (const float*)d_in[6];
    const float* be   = (const float*)d_in[7];
    const float* Wadd = (const float*)d_in[8];
    const float* badd = (const float*)d_in[9];
    const float* Wa   = (const float*)d_in[10];
    const float* ba   = (const float*)d_in[11];
    const float* Wf   = (const float*)d_in[12];
    const float* bf   = (const float*)d_in[13];
    const float* Wih  = (const float*)d_in[14];
    const float* Whh  = (const float*)d_in[15];
    const float* bih  = (const float*)d_in[16];
    const float* bhh  = (const float*)d_in[17];
    const float* hx0  = (const float*)d_in[18];
    const float* cx0  = (const float*)d_in[19];
    const float* Wp   = (const float*)d_in[20];
    const float* bp   = (const float*)d_in[21];
    float* out = (float*)d_out;

    static bool attr_set = false;
    if (!attr_set) {
        cudaFuncSetAttribute(k_persist, cudaFuncAttributeMaxDynamicSharedMemorySize, SMEM_BYTES);
        attr_set = true;
    }
    k_persist<<<NBLK, NTHR, SMEM_BYTES>>>(q, r, Mk, Mv0, ktab, xtab, We, be, Wadd, badd,
                                          Wa, ba, Wf, bf, Wih, Whh, bih, bhh,
                                          hx0, cx0, Wp, bp, out);
}